// round 2
// baseline (speedup 1.0000x reference)
#include <cuda_runtime.h>
#include <math.h>

// ---------------- problem constants ----------------
#define NNODES 325
#define BATCH  64
#define TSTEPS 12
#define HORIZON 12
#define UNITS  64
#define DIN    2

#define NB (NNODES*BATCH)        // 20800 rows
#define F3MAX 384
#define MAXNNZ 110000            // >= N*N, cannot overflow

// ---------------- device scratch (no allocs allowed) ----------------
__device__ float g_h0[NB*UNITS];     // layer-0 hidden (enc then dec)
__device__ float g_h1[NB*UNITS];     // layer-1 hidden (enc then dec)
__device__ float g_din[NB];          // decoder input (DOUT=1)
__device__ float g_xk[NB*F3MAX];     // concat + diffusion workspace, row stride F3
__device__ float g_ru[NB*2*UNITS];   // gate outputs (only u half [64,128) used)
__device__ int   g_rowptr[NNODES+1];
__device__ int   g_cols[MAXNNZ];
__device__ float g_vals[MAXNNZ];

// ---------------- f32x2 packed-FMA helpers (sm_103a) ----------------
typedef unsigned long long ull;
__device__ __forceinline__ ull pk2(float x, float y){
    ull r; asm("mov.b64 %0,{%1,%2};" : "=l"(r) : "f"(x), "f"(y)); return r;
}
__device__ __forceinline__ void upk2(ull v, float &x, float &y){
    asm("mov.b64 {%0,%1},%2;" : "=f"(x), "=f"(y) : "l"(v));
}
__device__ __forceinline__ void fma2(ull &acc, ull a, ull b){
    asm("fma.rn.f32x2 %0,%1,%2,%0;" : "+l"(acc) : "l"(a), "l"(b));
}

// ---------------- CSR build (support is ~2% sparse; exact-zero skip) ----------------
__global__ void build_csr(const float* __restrict__ S){
    __shared__ int cnt[NNODES+1];
    int t = threadIdx.x;
    for (int r = t; r < NNODES; r += blockDim.x){
        int c = 0;
        for (int j = 0; j < NNODES; j++) c += (S[r*NNODES + j] != 0.0f);
        cnt[r] = c;
    }
    __syncthreads();
    if (t == 0){
        int acc = 0;
        for (int r = 0; r < NNODES; r++){ int c = cnt[r]; cnt[r] = acc; acc += c; }
        cnt[NNODES] = acc;
    }
    __syncthreads();
    for (int r = t; r <= NNODES; r += blockDim.x) g_rowptr[r] = cnt[r];
    for (int r = t; r < NNODES; r += blockDim.x){
        int p = cnt[r];
        for (int j = 0; j < NNODES; j++){
            float v = S[r*NNODES + j];
            if (v != 0.0f){ g_cols[p] = j; g_vals[p] = v; p++; }
        }
    }
}

// ---------------- zero initial state ----------------
__global__ void zero_state(){
    int i = blockIdx.x*blockDim.x + threadIdx.x;
    if (i < NB*UNITS){ g_h0[i] = 0.f; g_h1[i] = 0.f; }
    if (i < NB) g_din[i] = 0.f;
}

// ---------------- concat kernels (write x0 = [x, h] into xk[...,0:F]) ----------------
// enc0: x comes from inputs[t] with layout (B, N*DIN); h = g_h0. F = 66, F3 = 198.
__global__ void concat_enc0(const float* __restrict__ inp_t){
    const int F = DIN + UNITS, F3 = 3*F;
    int idx = blockIdx.x*blockDim.x + threadIdx.x;
    if (idx >= NB*F) return;
    int f  = idx % F;
    int nb = idx / F;          // nb = n*BATCH + b
    int b  = nb % BATCH;
    int n  = nb / BATCH;
    float v;
    if (f < DIN) v = inp_t[b*(NNODES*DIN) + n*DIN + f];
    else         v = g_h0[nb*UNITS + (f - DIN)];
    g_xk[nb*F3 + f] = v;
}

// generic: x from buffer (g_h0 or g_din), h from selected state
__global__ void concat_buf(int xsel /*0:g_h0 1:g_din*/, int Fx, int hsel){
    const float* X = xsel ? g_din : g_h0;
    const float* H = hsel ? g_h1  : g_h0;
    int F = Fx + UNITS, F3 = 3*F;
    int idx = blockIdx.x*blockDim.x + threadIdx.x;
    if (idx >= NB*F) return;
    int f  = idx % F;
    int nb = idx / F;
    float v = (f < Fx) ? X[nb*Fx + f] : H[nb*UNITS + (f - Fx)];
    g_xk[nb*F3 + f] = v;
}

// ---------------- sparse diffusion: y[m] = sum_k S[m,k] x[k]  (optionally 2*y - x0) ----------------
__global__ void spmm(int F3, int in_off, int out_off, int ncols, int cheb_off /* <0: plain */){
    int m = blockIdx.y;
    int c = blockIdx.x*blockDim.x + threadIdx.x;
    if (c >= BATCH*ncols) return;
    int b = c / ncols, f = c % ncols;
    int s0 = g_rowptr[m], s1 = g_rowptr[m+1];
    float acc = 0.f;
    for (int j = s0; j < s1; j++){
        int k = g_cols[j];
        acc += g_vals[j] * g_xk[(k*BATCH + b)*F3 + in_off + f];
    }
    int orow = (m*BATCH + b)*F3;
    if (cheb_off >= 0) acc = 2.f*acc - g_xk[orow + cheb_off + f];
    g_xk[orow + out_off + f] = acc;
}

// ---------------- weight GEMM with fused GRU epilogues ----------------
// C = A(g_xk: NB x F3) @ W(F3 x ONUM) + bias
// epi 0 (gate, ONUM=128): s = sigmoid(v); cols<64: xk[row][Fx+col] = s * H  (r*h)
//                                         cols>=64: g_ru[row][col] = s      (u)
// epi 1 (cand, ONUM=64):  c = tanh(v); H = u*H + (1-u)*c  (in place)
#define BM 128
#define BK 16

template<int ONUM>
__global__ __launch_bounds__(256)
void gemm_act(int F3, const float* __restrict__ W, const float* __restrict__ bias,
              int hsel, int epi, int Fx)
{
    const int NPT = ONUM/16;                 // cols per thread: 8 or 4
    __shared__ float As[BK][BM+4];
    __shared__ float Bs[BK][ONUM];
    float* H = hsel ? g_h1 : g_h0;

    int tid = threadIdx.x;
    int tx = tid & 15, ty = tid >> 4;
    int row0 = blockIdx.x*BM;

    ull acc[8][NPT/2];
    #pragma unroll
    for (int i = 0; i < 8; i++)
        #pragma unroll
        for (int j = 0; j < NPT/2; j++) acc[i][j] = 0ull;

    int ktiles = (F3 + BK - 1)/BK;
    for (int kt = 0; kt < ktiles; kt++){
        int k0 = kt*BK;
        #pragma unroll
        for (int l = 0; l < (BM*BK)/256; l++){
            int idx = l*256 + tid;
            int kk = idx & 15, mm = idx >> 4;
            int r = row0 + mm, k = k0 + kk;
            As[kk][mm] = (r < NB && k < F3) ? g_xk[r*F3 + k] : 0.f;
        }
        #pragma unroll
        for (int l = 0; l < (ONUM*BK)/256; l++){
            int idx = l*256 + tid;
            int n = idx % ONUM, kk = idx / ONUM;
            int k = k0 + kk;
            Bs[kk][n] = (k < F3) ? W[k*ONUM + n] : 0.f;
        }
        __syncthreads();
        #pragma unroll
        for (int kk = 0; kk < BK; kk++){
            float4 av0 = *(const float4*)&As[kk][ty*8];
            float4 av1 = *(const float4*)&As[kk][ty*8 + 4];
            float a8[8] = {av0.x, av0.y, av0.z, av0.w, av1.x, av1.y, av1.z, av1.w};
            ull b2[NPT/2];
            #pragma unroll
            for (int j = 0; j < NPT/4; j++){
                float4 bv = *(const float4*)&Bs[kk][tx*NPT + j*4];
                b2[2*j]   = pk2(bv.x, bv.y);
                b2[2*j+1] = pk2(bv.z, bv.w);
            }
            #pragma unroll
            for (int i = 0; i < 8; i++){
                ull aa = pk2(a8[i], a8[i]);
                #pragma unroll
                for (int j = 0; j < NPT/2; j++) fma2(acc[i][j], aa, b2[j]);
            }
        }
        __syncthreads();
    }

    #pragma unroll
    for (int i = 0; i < 8; i++){
        int r = row0 + ty*8 + i;
        if (r >= NB) continue;
        #pragma unroll
        for (int j = 0; j < NPT/2; j++){
            float v0, v1; upk2(acc[i][j], v0, v1);
            int n0 = tx*NPT + 2*j;
            v0 += bias[n0]; v1 += bias[n0+1];
            if (epi == 0){
                float s0 = 1.f/(1.f + expf(-v0));
                float s1 = 1.f/(1.f + expf(-v1));
                if (n0 < UNITS){   // r: write r*h into concat buffer for cand gconv
                    g_xk[r*F3 + Fx + n0]     = s0 * H[r*UNITS + n0];
                    g_xk[r*F3 + Fx + n0 + 1] = s1 * H[r*UNITS + n0 + 1];
                } else {           // u
                    g_ru[r*(2*UNITS) + n0]     = s0;
                    g_ru[r*(2*UNITS) + n0 + 1] = s1;
                }
            } else {
                float c0 = tanhf(v0), c1 = tanhf(v1);
                float u0 = g_ru[r*(2*UNITS) + UNITS + n0];
                float u1 = g_ru[r*(2*UNITS) + UNITS + n0 + 1];
                float h0v = H[r*UNITS + n0], h1v = H[r*UNITS + n0 + 1];
                H[r*UNITS + n0]     = u0*h0v + (1.f - u0)*c0;
                H[r*UNITS + n0 + 1] = u1*h1v + (1.f - u1)*c1;
            }
        }
    }
}

// ---------------- projection: out = h1 @ proj_W + proj_b ; also next decoder input ----------------
__global__ void proj_kernel(const float* __restrict__ pW, const float* __restrict__ pb,
                            float* __restrict__ out_t){
    int nb = blockIdx.x*8 + threadIdx.y;     // < NB exactly (2600*8)
    int lane = threadIdx.x;
    float v = g_h1[nb*UNITS + lane]      * pW[lane]
            + g_h1[nb*UNITS + 32 + lane] * pW[32 + lane];
    #pragma unroll
    for (int o = 16; o > 0; o >>= 1) v += __shfl_down_sync(0xffffffffu, v, o);
    if (lane == 0){
        v += pb[0];
        int n = nb / BATCH, b = nb % BATCH;
        out_t[b*NNODES + n] = v;
        g_din[nb] = v;
    }
}

// ---------------- host-side cell orchestration ----------------
static void launch_cell(const float* x_inp /*enc0 only, else null*/,
                        int xsel, int Fx, int hsel,
                        const float* gW, const float* gb,
                        const float* cW, const float* cb)
{
    int F = Fx + UNITS, F3 = 3*F;
    if (x_inp) concat_enc0<<<(NB*F + 255)/256, 256>>>(x_inp);
    else       concat_buf<<<(NB*F + 255)/256, 256>>>(xsel, Fx, hsel);
    // gate gconv: x1 = S x0 ; x2 = 2 S x1 - x0 (full F columns)
    spmm<<<dim3((BATCH*F + 255)/256, NNODES), 256>>>(F3, 0, F,   F, -1);
    spmm<<<dim3((BATCH*F + 255)/256, NNODES), 256>>>(F3, F, 2*F, F,  0);
    // gate GEMM: sigmoid; writes u to g_ru, r*h into xk h-columns
    gemm_act<2*UNITS><<<(NB + BM - 1)/BM, 256>>>(F3, gW, gb, hsel, 0, Fx);
    // cand gconv: only h-columns need re-diffusion (x-columns reused from gate phase)
    spmm<<<dim3((BATCH*UNITS + 255)/256, NNODES), 256>>>(F3, Fx,     F + Fx,   UNITS, -1);
    spmm<<<dim3((BATCH*UNITS + 255)/256, NNODES), 256>>>(F3, F + Fx, 2*F + Fx, UNITS, Fx);
    // cand GEMM: tanh + GRU combine, in-place H update
    gemm_act<UNITS><<<(NB + BM - 1)/BM, 256>>>(F3, cW, cb, hsel, 1, Fx);
}

extern "C" void kernel_launch(void* const* d_in, const int* in_sizes, int n_in,
                              void* d_out, int out_size)
{
    const float* inputs  = (const float*)d_in[0];   // (T, B, N*DIN)
    const float* support = (const float*)d_in[1];   // (N, N)
    const float* e0gW = (const float*)d_in[2];  const float* e0gb = (const float*)d_in[3];
    const float* e0cW = (const float*)d_in[4];  const float* e0cb = (const float*)d_in[5];
    const float* e1gW = (const float*)d_in[6];  const float* e1gb = (const float*)d_in[7];
    const float* e1cW = (const float*)d_in[8];  const float* e1cb = (const float*)d_in[9];
    const float* d0gW = (const float*)d_in[10]; const float* d0gb = (const float*)d_in[11];
    const float* d0cW = (const float*)d_in[12]; const float* d0cb = (const float*)d_in[13];
    const float* d1gW = (const float*)d_in[14]; const float* d1gb = (const float*)d_in[15];
    const float* d1cW = (const float*)d_in[16]; const float* d1cb = (const float*)d_in[17];
    const float* pW   = (const float*)d_in[18]; const float* pb   = (const float*)d_in[19];
    float* out = (float*)d_out;                     // (HZ, B, N)

    build_csr<<<1, 352>>>(support);
    zero_state<<<(NB*UNITS + 255)/256, 256>>>();

    // ---- encoder ----
    for (int t = 0; t < TSTEPS; t++){
        const float* inp_t = inputs + (size_t)t * BATCH * NNODES * DIN;
        launch_cell(inp_t, 0, DIN,   0, e0gW, e0gb, e0cW, e0cb);   // layer 0 -> g_h0
        launch_cell(nullptr, 0, UNITS, 1, e1gW, e1gb, e1cW, e1cb); // layer 1 -> g_h1
    }

    // ---- decoder (states carried over in g_h0/g_h1; g_din starts as GO=0) ----
    for (int t = 0; t < HORIZON; t++){
        launch_cell(nullptr, 1, 1,     0, d0gW, d0gb, d0cW, d0cb); // x = g_din
        launch_cell(nullptr, 0, UNITS, 1, d1gW, d1gb, d1cW, d1cb);
        proj_kernel<<<NB/8, dim3(32, 8)>>>(pW, pb, out + (size_t)t * BATCH * NNODES);
    }
}